// round 9
// baseline (speedup 1.0000x reference)
#include <cuda_runtime.h>
#include <cstdint>

// ---------------------------------------------------------------------------
// HeavyCompressor round 9: v8 with KT=64 (2-stage ring, 192 KB) to halve
// barrier count again. Stage rows = 64 tf32 = 256B = 16 cells of 16B,
// swizzle cell ^= (row & 7) (permutes within 128B half-rows; conflict-free).
//   CTA: 128 rows x 256 cols (c | z), 512 threads, warp tile 64x32.
//   B pre-converted to tf32 (device scratch) + cp.async; A LDG->cvt->STS.
// ---------------------------------------------------------------------------

constexpr int D_     = 2048;
constexpr int HD_    = 128;
constexpr int CTA_M  = 128;
constexpr int KT     = 64;
constexpr int NK     = D_ / KT;                 // 32
constexpr int A_BYTES = CTA_M * 256;            // 32 KB
constexpr int B_BYTES = 256 * 256;              // 64 KB
constexpr int STAGE_BYTES = A_BYTES + B_BYTES;  // 96 KB
constexpr int EPI_STR = 276;
constexpr int SMEM_BYTES = 2 * STAGE_BYTES;     // 196608 (> 138KB epilogue)

__device__ uint32_t g_wtf32[256 * 2048];        // pre-converted [wkv;wz] tf32 bits

__device__ __forceinline__ uint32_t f2tf(float f) {
    uint32_t r;
    asm("cvt.rna.tf32.f32 %0, %1;" : "=r"(r) : "f"(f));
    return r;
}
__device__ __forceinline__ uint32_t smem_u32(const void* p) {
    uint32_t a;
    asm("{ .reg .u64 t; cvta.to.shared.u64 t, %1; cvt.u32.u64 %0, t; }" : "=r"(a) : "l"(p));
    return a;
}
__device__ __forceinline__ void cp16(uint32_t dst, const void* src) {
    asm volatile("cp.async.cg.shared.global [%0], [%1], 16;" :: "r"(dst), "l"(src) : "memory");
}
__device__ __forceinline__ void ldsm4(uint32_t* r, uint32_t addr) {
    asm volatile("ldmatrix.sync.aligned.m8n8.x4.shared.b16 {%0,%1,%2,%3}, [%4];"
                 : "=r"(r[0]), "=r"(r[1]), "=r"(r[2]), "=r"(r[3]) : "r"(addr));
}
__device__ __forceinline__ void mma_tf32(float* c, uint32_t a0, uint32_t a1,
                                         uint32_t a2, uint32_t a3,
                                         uint32_t b0, uint32_t b1) {
    asm volatile(
        "mma.sync.aligned.m16n8k8.row.col.f32.tf32.tf32.f32 "
        "{%0,%1,%2,%3}, {%4,%5,%6,%7}, {%8,%9}, {%0,%1,%2,%3};"
        : "+f"(c[0]), "+f"(c[1]), "+f"(c[2]), "+f"(c[3])
        : "r"(a0), "r"(a1), "r"(a2), "r"(a3), "r"(b0), "r"(b1));
}

__global__ void convert_w(const float4* __restrict__ wkv, const float4* __restrict__ wz) {
    int i = blockIdx.x * blockDim.x + threadIdx.x;      // 0..131071 float4s
    int row = i >> 9, c4 = i & 511;
    float4 v = (row < 128) ? wkv[row * 512 + c4] : wz[(row - 128) * 512 + c4];
    ((uint4*)g_wtf32)[i] = make_uint4(f2tf(v.x), f2tf(v.y), f2tf(v.z), f2tf(v.w));
}

__global__ __launch_bounds__(512, 1)
void heavy_compressor_v9(const float* __restrict__ h,
                         const float* __restrict__ bias,
                         float* __restrict__ out,
                         int write_second, int out_half)
{
    extern __shared__ char smem[];
    const uint32_t sbase = smem_u32(smem);

    const int tid  = threadIdx.x;
    const int wid  = tid >> 5;
    const int lane = tid & 31;
    const int g    = lane >> 2;
    const int tg   = lane & 3;
    const int warp_m = wid & 1;            // 2 x 64 rows
    const int warp_n = wid >> 1;           // 8 x 32 cols
    const long long row0 = (long long)blockIdx.x * CTA_M;

    float acc[4][4][4];
#pragma unroll
    for (int mi = 0; mi < 4; ++mi)
#pragma unroll
        for (int ni = 0; ni < 4; ++ni)
#pragma unroll
            for (int j = 0; j < 4; ++j) acc[mi][ni][j] = 0.f;

    // ---- A loader: 512 threads, 16 k (4 float4 -> 4 cells) each ----
    const int arow = tid >> 2, aq = tid & 3;            // row 0..127, k-quarter(16)
    const float* asrc = h + (row0 + arow) * D_ + aq * 16;
    const int ae = arow & 7;
    // cell c = 4*aq + j, offset = arow*256 + ((c ^ ae) * 16)
    uint32_t aoff[4];
#pragma unroll
    for (int j = 0; j < 4; ++j) aoff[j] = arow * 256 + (((4 * aq + j) ^ ae) * 16);
    float4 ra[4];

    auto ldg_a = [&](int s) {
#pragma unroll
        for (int j = 0; j < 4; ++j) ra[j] = *(const float4*)(asrc + s * KT + j * 4);
    };
    auto sts_a = [&](int buf) {
        char* base = smem + buf * STAGE_BYTES;
#pragma unroll
        for (int j = 0; j < 4; ++j)
            *(uint4*)(base + aoff[j]) =
                make_uint4(f2tf(ra[j].x), f2tf(ra[j].y), f2tf(ra[j].z), f2tf(ra[j].w));
    };

    // ---- B cp.async: 4096 cells/stage, 8 per thread (affine in i) ----
    // idx = i*512 + tid ; brow = idx>>4 = i*32 + (tid>>4) ; kc = tid & 15
    const int btr = tid >> 4;                           // 0..31
    const int bkc = tid & 15;
    const uint32_t* bsrc0 = g_wtf32 + btr * 2048 + bkc * 4;        // + i*32*2048
    const uint32_t bdst0 = A_BYTES + btr * 256 + ((bkc ^ (btr & 7)) * 16);  // + i*8192
    auto cp_b = [&](int s) {
        const uint32_t base = sbase + (s & 1) * STAGE_BYTES + bdst0;
        const uint32_t* src = bsrc0 + s * KT;
#pragma unroll
        for (int i = 0; i < 8; ++i) cp16(base + i * 8192, src + i * 65536);
    };

    // ---- ldsm lane-constant pieces: off(ks) = P + ((ks ^ KSX) << 5) ----
    const int l7   = lane & 7;
    const int KSX  = l7 >> 1;
    const int row16  = (lane & 7) | (((lane >> 3) & 1) << 3);
    const int hiA    = lane >> 4;
    const int brow16 = (lane & 7) | ((lane >> 4) << 3);
    const int hiB    = (lane >> 3) & 1;
    const uint32_t PA = row16 * 256 + ((hiA ^ (l7 & 1)) * 16) + warp_m * 16384;
    const uint32_t PB = A_BYTES + brow16 * 256 + ((hiB ^ (l7 & 1)) * 16) + warp_n * 8192;

    // ---- prologue ----
    ldg_a(0);
    sts_a(0);
    cp_b(0);
    asm volatile("cp.async.commit_group;" ::: "memory");
    ldg_a(1);

    // ---- mainloop ----
#pragma unroll 1
    for (int t = 0; t < NK; ++t) {
        asm volatile("cp.async.wait_group 0;" ::: "memory");
        __syncthreads();

        if (t + 1 < NK) {
            sts_a((t + 1) & 1);
            cp_b(t + 1);
            asm volatile("cp.async.commit_group;" ::: "memory");
            if (t + 2 < NK) ldg_a(t + 2);
        }

        const uint32_t cs = sbase + (t & 1) * STAGE_BYTES;
#pragma unroll
        for (int ks = 0; ks < 8; ++ks) {
            const uint32_t kx = (uint32_t)((ks ^ KSX) << 5);
            uint32_t a[4][4], b[2][4];
#pragma unroll
            for (int mi = 0; mi < 4; ++mi)
                ldsm4(a[mi], cs + PA + mi * 4096 + kx);
#pragma unroll
            for (int np = 0; np < 2; ++np)
                ldsm4(b[np], cs + PB + np * 4096 + kx);
#pragma unroll
            for (int mi = 0; mi < 4; ++mi)
#pragma unroll
                for (int ni = 0; ni < 4; ++ni)
                    mma_tf32(acc[mi][ni],
                             a[mi][0], a[mi][1], a[mi][2], a[mi][3],
                             b[ni >> 1][(ni & 1) * 2], b[ni >> 1][(ni & 1) * 2 + 1]);
        }
    }

    // ---- epilogue: accums -> smem, windowed softmax-compress ----
    float* epi = (float*)smem;
    __syncthreads();
#pragma unroll
    for (int mi = 0; mi < 4; ++mi)
#pragma unroll
        for (int ni = 0; ni < 4; ++ni) {
            int m0 = warp_m * 64 + mi * 16 + g;
            int n0 = warp_n * 32 + ni * 8 + 2 * tg;
            *(float2*)(epi + m0 * EPI_STR + n0)       = make_float2(acc[mi][ni][0], acc[mi][ni][1]);
            *(float2*)(epi + (m0 + 8) * EPI_STR + n0) = make_float2(acc[mi][ni][2], acc[mi][ni][3]);
        }
    __syncthreads();

    const int win = tid >> 5;            // 16 windows of 8 rows
    float zb[8][4], cc[8][4];
#pragma unroll
    for (int r = 0; r < 8; ++r) {
        const float* rp = epi + (win * 8 + r) * EPI_STR;
        float4 c4 = *(const float4*)(rp + lane * 4);
        float4 z4 = *(const float4*)(rp + HD_ + lane * 4);
        float4 b4 = *(const float4*)(bias + r * HD_ + lane * 4);
        cc[r][0] = c4.x; cc[r][1] = c4.y; cc[r][2] = c4.z; cc[r][3] = c4.w;
        zb[r][0] = z4.x + b4.x; zb[r][1] = z4.y + b4.y;
        zb[r][2] = z4.z + b4.z; zb[r][3] = z4.w + b4.w;
    }
    float res[4];
#pragma unroll
    for (int i = 0; i < 4; ++i) {
        float mx = zb[0][i];
#pragma unroll
        for (int r = 1; r < 8; ++r) mx = fmaxf(mx, zb[r][i]);
        float s = 0.f, a = 0.f;
#pragma unroll
        for (int r = 0; r < 8; ++r) {
            float e = __expf(zb[r][i] - mx);
            s += e;
            a = fmaf(e, cc[r][i], a);
        }
        res[i] = a / s;
    }
    const long long w = (long long)blockIdx.x * 16 + win;
    float4 v = make_float4(res[0], res[1], res[2], res[3]);
    float* dst = out + w * HD_ + lane * 4;
    *(float4*)dst = v;
    if (write_second) *(float4*)(dst + out_half) = v;
}

extern "C" void kernel_launch(void* const* d_in, const int* in_sizes, int n_in,
                              void* d_out, int out_size)
{
    const float* h    = (const float*)d_in[0];
    const float* wkv  = (const float*)d_in[1];
    const float* wz   = (const float*)d_in[2];
    const float* bias = (const float*)d_in[3];

    const int rows = in_sizes[0] / D_;              // 32768
    const int base = (rows / 8) * HD_;              // 524288
    const int write_second = (out_size >= 2 * base) ? 1 : 0;

    convert_w<<<512, 256>>>((const float4*)wkv, (const float4*)wz);

    cudaFuncSetAttribute(heavy_compressor_v9,
                         cudaFuncAttributeMaxDynamicSharedMemorySize, SMEM_BYTES);
    heavy_compressor_v9<<<rows / CTA_M, 512, SMEM_BYTES>>>(
        h, bias, (float*)d_out, write_second, base);
}

// round 10
// speedup vs baseline: 1.1616x; 1.1616x over previous
#include <cuda_runtime.h>
#include <cstdint>

// ---------------------------------------------------------------------------
// HeavyCompressor round 10: v8 skeleton (KT=32, 3-stage ring, ldsm + tf32
// mma) with the A-convert path deleted: HMMA.tf32 ignores the low 13 mantissa
// bits, so A streams as raw fp32 bits via cp.async (truncation ~2^-12 bias;
// B stays rna-preconverted). Frees ~20 regs -> ptxas can pipeline ldsm/mma.
//   CTA: 128 rows x 256 cols (c | z), 512 threads, warp tile 64x32.
//   Stage rows = 32 words = 128B = 8 cells of 16B, cell ^= (row & 7).
// ---------------------------------------------------------------------------

constexpr int D_     = 2048;
constexpr int HD_    = 128;
constexpr int CTA_M  = 128;
constexpr int KT     = 32;
constexpr int NK     = D_ / KT;                 // 64
constexpr int A_BYTES = CTA_M * 128;            // 16 KB
constexpr int B_BYTES = 256 * 128;              // 32 KB
constexpr int STAGE_BYTES = A_BYTES + B_BYTES;  // 48 KB
constexpr int EPI_STR = 276;
constexpr int SMEM_BYTES = 3 * STAGE_BYTES;     // 147456 (> 138KB epilogue)

__device__ uint32_t g_wtf32[256 * 2048];        // rna-preconverted [wkv;wz]

__device__ __forceinline__ uint32_t f2tf(float f) {
    uint32_t r;
    asm("cvt.rna.tf32.f32 %0, %1;" : "=r"(r) : "f"(f));
    return r;
}
__device__ __forceinline__ uint32_t smem_u32(const void* p) {
    uint32_t a;
    asm("{ .reg .u64 t; cvta.to.shared.u64 t, %1; cvt.u32.u64 %0, t; }" : "=r"(a) : "l"(p));
    return a;
}
__device__ __forceinline__ void cp16(uint32_t dst, const void* src) {
    asm volatile("cp.async.cg.shared.global [%0], [%1], 16;" :: "r"(dst), "l"(src) : "memory");
}
__device__ __forceinline__ void ldsm4(uint32_t* r, uint32_t addr) {
    asm volatile("ldmatrix.sync.aligned.m8n8.x4.shared.b16 {%0,%1,%2,%3}, [%4];"
                 : "=r"(r[0]), "=r"(r[1]), "=r"(r[2]), "=r"(r[3]) : "r"(addr));
}
__device__ __forceinline__ void mma_tf32(float* c, uint32_t a0, uint32_t a1,
                                         uint32_t a2, uint32_t a3,
                                         uint32_t b0, uint32_t b1) {
    asm volatile(
        "mma.sync.aligned.m16n8k8.row.col.f32.tf32.tf32.f32 "
        "{%0,%1,%2,%3}, {%4,%5,%6,%7}, {%8,%9}, {%0,%1,%2,%3};"
        : "+f"(c[0]), "+f"(c[1]), "+f"(c[2]), "+f"(c[3])
        : "r"(a0), "r"(a1), "r"(a2), "r"(a3), "r"(b0), "r"(b1));
}

__global__ void convert_w(const float4* __restrict__ wkv, const float4* __restrict__ wz) {
    int i = blockIdx.x * blockDim.x + threadIdx.x;      // 0..131071 float4s
    int row = i >> 9, c4 = i & 511;
    float4 v = (row < 128) ? wkv[row * 512 + c4] : wz[(row - 128) * 512 + c4];
    ((uint4*)g_wtf32)[i] = make_uint4(f2tf(v.x), f2tf(v.y), f2tf(v.z), f2tf(v.w));
}

__global__ __launch_bounds__(512, 1)
void heavy_compressor_v10(const float* __restrict__ h,
                          const float* __restrict__ bias,
                          float* __restrict__ out,
                          int write_second, int out_half)
{
    extern __shared__ char smem[];
    const uint32_t sbase = smem_u32(smem);

    const int tid  = threadIdx.x;
    const int wid  = tid >> 5;
    const int lane = tid & 31;
    const int g    = lane >> 2;
    const int tg   = lane & 3;
    const int warp_m = wid & 1;            // 2 x 64 rows
    const int warp_n = wid >> 1;           // 8 x 32 cols
    const long long row0 = (long long)blockIdx.x * CTA_M;

    float acc[4][4][4];
#pragma unroll
    for (int mi = 0; mi < 4; ++mi)
#pragma unroll
        for (int ni = 0; ni < 4; ++ni)
#pragma unroll
            for (int j = 0; j < 4; ++j) acc[mi][ni][j] = 0.f;

    // ---- A cp.async: 1024 cells/stage, 2 per thread (raw fp32 bits) ----
    const int ar0 = tid >> 3, akc0 = tid & 7;                     // i=0
    const int ar1 = (tid + 512) >> 3, akc1 = tid & 7;             // i=1
    const float* asrc0 = h + (row0 + ar0) * D_ + akc0 * 4;
    const float* asrc1 = h + (row0 + ar1) * D_ + akc1 * 4;
    const uint32_t adst0 = ar0 * 128 + ((akc0 ^ (ar0 & 7)) * 16);
    const uint32_t adst1 = ar1 * 128 + ((akc1 ^ (ar1 & 7)) * 16);

    // ---- B cp.async: 2048 cells/stage, 4 per thread (tf32-rna bits) ----
    uint32_t bdst[4];
    const uint32_t* bsrc[4];
#pragma unroll
    for (int i = 0; i < 4; ++i) {
        int idx = i * 512 + tid;
        int brow = idx >> 3, kc = idx & 7;
        bsrc[i] = g_wtf32 + brow * 2048 + kc * 4;
        bdst[i] = A_BYTES + brow * 128 + ((kc ^ (brow & 7)) * 16);
    }

    auto cp_stage = [&](int s) {
        const uint32_t base = sbase + (s % 3) * STAGE_BYTES;
        const int k0 = s * KT;
        cp16(base + adst0, asrc0 + k0);
        cp16(base + adst1, asrc1 + k0);
#pragma unroll
        for (int i = 0; i < 4; ++i) cp16(base + bdst[i], bsrc[i] + k0);
        asm volatile("cp.async.commit_group;" ::: "memory");
    };

    // ---- ldsm lane-constant offsets (cell ^= row&7) ----
    const int row16  = (lane & 7) | (((lane >> 3) & 1) << 3);
    const int hiA    = lane >> 4;
    const int brow16 = (lane & 7) | ((lane >> 4) << 3);
    const int hiB    = (lane >> 3) & 1;
    const int l7     = lane & 7;
    int offA[4], offB[4];
#pragma unroll
    for (int ks = 0; ks < 4; ++ks) {
        offA[ks] = row16  * 128 + (((2 * ks + hiA) ^ l7) * 16);
        offB[ks] = brow16 * 128 + (((2 * ks + hiB) ^ l7) * 16);
    }
    const uint32_t aW = warp_m * 8192;                  // 64 rows * 128B
    const uint32_t bW = A_BYTES + warp_n * 4096;        // 32 rows * 128B

    // ---- prologue ----
    cp_stage(0);
    cp_stage(1);

    // ---- mainloop ----
#pragma unroll 1
    for (int t = 0; t < NK; ++t) {
        asm volatile("cp.async.wait_group 1;" ::: "memory");
        __syncthreads();

        if (t + 2 < NK) cp_stage(t + 2);
        else asm volatile("cp.async.commit_group;" ::: "memory");

        const uint32_t cs = sbase + (t % 3) * STAGE_BYTES;
#pragma unroll
        for (int ks = 0; ks < 4; ++ks) {
            uint32_t a[4][4], b[2][4];
#pragma unroll
            for (int mi = 0; mi < 4; ++mi)
                ldsm4(a[mi], cs + aW + mi * 2048 + offA[ks]);
#pragma unroll
            for (int np = 0; np < 2; ++np)
                ldsm4(b[np], cs + bW + np * 2048 + offB[ks]);
#pragma unroll
            for (int mi = 0; mi < 4; ++mi)
#pragma unroll
                for (int ni = 0; ni < 4; ++ni)
                    mma_tf32(acc[mi][ni],
                             a[mi][0], a[mi][1], a[mi][2], a[mi][3],
                             b[ni >> 1][(ni & 1) * 2], b[ni >> 1][(ni & 1) * 2 + 1]);
        }
    }

    // ---- epilogue: accums -> smem, windowed softmax-compress ----
    float* epi = (float*)smem;
    __syncthreads();
#pragma unroll
    for (int mi = 0; mi < 4; ++mi)
#pragma unroll
        for (int ni = 0; ni < 4; ++ni) {
            int m0 = warp_m * 64 + mi * 16 + g;
            int n0 = warp_n * 32 + ni * 8 + 2 * tg;
            *(float2*)(epi + m0 * EPI_STR + n0)       = make_float2(acc[mi][ni][0], acc[mi][ni][1]);
            *(float2*)(epi + (m0 + 8) * EPI_STR + n0) = make_float2(acc[mi][ni][2], acc[mi][ni][3]);
        }
    __syncthreads();

    const int win = tid >> 5;            // 16 windows of 8 rows
    float zb[8][4], cc[8][4];
#pragma unroll
    for (int r = 0; r < 8; ++r) {
        const float* rp = epi + (win * 8 + r) * EPI_STR;
        float4 c4 = *(const float4*)(rp + lane * 4);
        float4 z4 = *(const float4*)(rp + HD_ + lane * 4);
        float4 b4 = *(const float4*)(bias + r * HD_ + lane * 4);
        cc[r][0] = c4.x; cc[r][1] = c4.y; cc[r][2] = c4.z; cc[r][3] = c4.w;
        zb[r][0] = z4.x + b4.x; zb[r][1] = z4.y + b4.y;
        zb[r][2] = z4.z + b4.z; zb[r][3] = z4.w + b4.w;
    }
    float res[4];
#pragma unroll
    for (int i = 0; i < 4; ++i) {
        float mx = zb[0][i];
#pragma unroll
        for (int r = 1; r < 8; ++r) mx = fmaxf(mx, zb[r][i]);
        float s = 0.f, a = 0.f;
#pragma unroll
        for (int r = 0; r < 8; ++r) {
            float e = __expf(zb[r][i] - mx);
            s += e;
            a = fmaf(e, cc[r][i], a);
        }
        res[i] = a / s;
    }
    const long long w = (long long)blockIdx.x * 16 + win;
    float4 v = make_float4(res[0], res[1], res[2], res[3]);
    float* dst = out + w * HD_ + lane * 4;
    *(float4*)dst = v;
    if (write_second) *(float4*)(dst + out_half) = v;
}

extern "C" void kernel_launch(void* const* d_in, const int* in_sizes, int n_in,
                              void* d_out, int out_size)
{
    const float* h    = (const float*)d_in[0];
    const float* wkv  = (const float*)d_in[1];
    const float* wz   = (const float*)d_in[2];
    const float* bias = (const float*)d_in[3];

    const int rows = in_sizes[0] / D_;              // 32768
    const int base = (rows / 8) * HD_;              // 524288
    const int write_second = (out_size >= 2 * base) ? 1 : 0;

    convert_w<<<512, 256>>>((const float4*)wkv, (const float4*)wz);

    cudaFuncSetAttribute(heavy_compressor_v10,
                         cudaFuncAttributeMaxDynamicSharedMemorySize, SMEM_BYTES);
    heavy_compressor_v10<<<rows / CTA_M, 512, SMEM_BYTES>>>(
        h, bias, (float*)d_out, write_second, base);
}

// round 11
// speedup vs baseline: 1.2000x; 1.0331x over previous
#include <cuda_runtime.h>
#include <cstdint>

// ---------------------------------------------------------------------------
// HeavyCompressor round 11: v10 all-cp.async skeleton with KT=64, 2-stage
// ring (192 KB) — halves barrier count. A streams as raw fp32 bits (HMMA
// tf32 reads top 19 bits), B pre-converted rna-tf32 in device scratch.
//   CTA: 128 rows x 256 cols (c | z), 512 threads, warp tile 64x32.
//   Stage rows = 64 words = 256B = 16 cells of 16B, cell ^= (row & 7).
// ---------------------------------------------------------------------------

constexpr int D_     = 2048;
constexpr int HD_    = 128;
constexpr int CTA_M  = 128;
constexpr int KT     = 64;
constexpr int NK     = D_ / KT;                 // 32
constexpr int A_BYTES = CTA_M * 256;            // 32 KB
constexpr int B_BYTES = 256 * 256;              // 64 KB
constexpr int STAGE_BYTES = A_BYTES + B_BYTES;  // 96 KB
constexpr int EPI_STR = 276;
constexpr int SMEM_BYTES = 2 * STAGE_BYTES;     // 196608 (> 138KB epilogue)

__device__ uint32_t g_wtf32[256 * 2048];        // rna-preconverted [wkv;wz]

__device__ __forceinline__ uint32_t f2tf(float f) {
    uint32_t r;
    asm("cvt.rna.tf32.f32 %0, %1;" : "=r"(r) : "f"(f));
    return r;
}
__device__ __forceinline__ uint32_t smem_u32(const void* p) {
    uint32_t a;
    asm("{ .reg .u64 t; cvta.to.shared.u64 t, %1; cvt.u32.u64 %0, t; }" : "=r"(a) : "l"(p));
    return a;
}
__device__ __forceinline__ void cp16(uint32_t dst, const void* src) {
    asm volatile("cp.async.cg.shared.global [%0], [%1], 16;" :: "r"(dst), "l"(src) : "memory");
}
__device__ __forceinline__ void ldsm4(uint32_t* r, uint32_t addr) {
    asm volatile("ldmatrix.sync.aligned.m8n8.x4.shared.b16 {%0,%1,%2,%3}, [%4];"
                 : "=r"(r[0]), "=r"(r[1]), "=r"(r[2]), "=r"(r[3]) : "r"(addr));
}
__device__ __forceinline__ void mma_tf32(float* c, uint32_t a0, uint32_t a1,
                                         uint32_t a2, uint32_t a3,
                                         uint32_t b0, uint32_t b1) {
    asm volatile(
        "mma.sync.aligned.m16n8k8.row.col.f32.tf32.tf32.f32 "
        "{%0,%1,%2,%3}, {%4,%5,%6,%7}, {%8,%9}, {%0,%1,%2,%3};"
        : "+f"(c[0]), "+f"(c[1]), "+f"(c[2]), "+f"(c[3])
        : "r"(a0), "r"(a1), "r"(a2), "r"(a3), "r"(b0), "r"(b1));
}

__global__ void convert_w(const float4* __restrict__ wkv, const float4* __restrict__ wz) {
    int i = blockIdx.x * blockDim.x + threadIdx.x;      // 0..131071 float4s
    int row = i >> 9, c4 = i & 511;
    float4 v = (row < 128) ? wkv[row * 512 + c4] : wz[(row - 128) * 512 + c4];
    ((uint4*)g_wtf32)[i] = make_uint4(f2tf(v.x), f2tf(v.y), f2tf(v.z), f2tf(v.w));
}

__global__ __launch_bounds__(512, 1)
void heavy_compressor_v11(const float* __restrict__ h,
                          const float* __restrict__ bias,
                          float* __restrict__ out,
                          int write_second, int out_half)
{
    extern __shared__ char smem[];
    const uint32_t sbase = smem_u32(smem);

    const int tid  = threadIdx.x;
    const int wid  = tid >> 5;
    const int lane = tid & 31;
    const int g    = lane >> 2;
    const int tg   = lane & 3;
    const int warp_m = wid & 1;            // 2 x 64 rows
    const int warp_n = wid >> 1;           // 8 x 32 cols
    const long long row0 = (long long)blockIdx.x * CTA_M;

    float acc[4][4][4];
#pragma unroll
    for (int mi = 0; mi < 4; ++mi)
#pragma unroll
        for (int ni = 0; ni < 4; ++ni)
#pragma unroll
            for (int j = 0; j < 4; ++j) acc[mi][ni][j] = 0.f;

    // ---- A cp.async: 2048 cells/stage, 4 per thread, affine in i ----
    // idx = i*512 + tid ; arow = i*32 + (tid>>4) ; akc = tid & 15
    const int atr = tid >> 4;                          // 0..31
    const int akc = tid & 15;
    const float* asrc0 = h + (row0 + atr) * D_ + akc * 4;          // + i*32 rows
    const uint32_t adst0 = atr * 256 + ((akc ^ (atr & 7)) * 16);   // + i*8192

    // ---- B cp.async: 4096 cells/stage, 8 per thread, affine in i ----
    const uint32_t* bsrc0 = g_wtf32 + atr * 2048 + akc * 4;        // + i*32*2048
    const uint32_t bdst0 = A_BYTES + adst0;                        // same swizzle

    auto cp_stage = [&](int s) {
        const uint32_t base = sbase + (s & 1) * STAGE_BYTES;
        const int k0 = s * KT;
        const float* as = asrc0 + k0;
        const uint32_t* bs = bsrc0 + k0;
#pragma unroll
        for (int i = 0; i < 4; ++i)
            cp16(base + adst0 + i * 8192, as + (long long)i * 32 * D_);
#pragma unroll
        for (int i = 0; i < 8; ++i)
            cp16(base + bdst0 + i * 8192, bs + i * 65536);
        asm volatile("cp.async.commit_group;" ::: "memory");
    };

    // ---- ldsm lane-constant pieces: off(ks) = P + ((ks ^ KSX) << 5) ----
    const int l7   = lane & 7;
    const int KSX  = l7 >> 1;
    const int row16  = (lane & 7) | (((lane >> 3) & 1) << 3);
    const int hiA    = lane >> 4;
    const int brow16 = (lane & 7) | ((lane >> 4) << 3);
    const int hiB    = (lane >> 3) & 1;
    const uint32_t PA = row16 * 256 + ((hiA ^ (l7 & 1)) * 16) + warp_m * 16384;
    const uint32_t PB = A_BYTES + brow16 * 256 + ((hiB ^ (l7 & 1)) * 16) + warp_n * 8192;

    // ---- prologue ----
    cp_stage(0);

    // ---- mainloop: one barrier per KT=64 tile ----
#pragma unroll 1
    for (int t = 0; t < NK; ++t) {
        asm volatile("cp.async.wait_group 0;" ::: "memory");
        __syncthreads();

        if (t + 1 < NK) cp_stage(t + 1);

        const uint32_t cs = sbase + (t & 1) * STAGE_BYTES;
#pragma unroll
        for (int ks = 0; ks < 8; ++ks) {
            const uint32_t kx = (uint32_t)((ks ^ KSX) << 5);
            uint32_t a[4][4], b[2][4];
#pragma unroll
            for (int mi = 0; mi < 4; ++mi)
                ldsm4(a[mi], cs + PA + mi * 4096 + kx);
#pragma unroll
            for (int np = 0; np < 2; ++np)
                ldsm4(b[np], cs + PB + np * 4096 + kx);
#pragma unroll
            for (int mi = 0; mi < 4; ++mi)
#pragma unroll
                for (int ni = 0; ni < 4; ++ni)
                    mma_tf32(acc[mi][ni],
                             a[mi][0], a[mi][1], a[mi][2], a[mi][3],
                             b[ni >> 1][(ni & 1) * 2], b[ni >> 1][(ni & 1) * 2 + 1]);
        }
    }

    // ---- epilogue: accums -> smem, windowed softmax-compress ----
    float* epi = (float*)smem;
    __syncthreads();
#pragma unroll
    for (int mi = 0; mi < 4; ++mi)
#pragma unroll
        for (int ni = 0; ni < 4; ++ni) {
            int m0 = warp_m * 64 + mi * 16 + g;
            int n0 = warp_n * 32 + ni * 8 + 2 * tg;
            *(float2*)(epi + m0 * EPI_STR + n0)       = make_float2(acc[mi][ni][0], acc[mi][ni][1]);
            *(float2*)(epi + (m0 + 8) * EPI_STR + n0) = make_float2(acc[mi][ni][2], acc[mi][ni][3]);
        }
    __syncthreads();

    const int win = tid >> 5;            // 16 windows of 8 rows
    float zb[8][4], cc[8][4];
#pragma unroll
    for (int r = 0; r < 8; ++r) {
        const float* rp = epi + (win * 8 + r) * EPI_STR;
        float4 c4 = *(const float4*)(rp + lane * 4);
        float4 z4 = *(const float4*)(rp + HD_ + lane * 4);
        float4 b4 = *(const float4*)(bias + r * HD_ + lane * 4);
        cc[r][0] = c4.x; cc[r][1] = c4.y; cc[r][2] = c4.z; cc[r][3] = c4.w;
        zb[r][0] = z4.x + b4.x; zb[r][1] = z4.y + b4.y;
        zb[r][2] = z4.z + b4.z; zb[r][3] = z4.w + b4.w;
    }
    float res[4];
#pragma unroll
    for (int i = 0; i < 4; ++i) {
        float mx = zb[0][i];
#pragma unroll
        for (int r = 1; r < 8; ++r) mx = fmaxf(mx, zb[r][i]);
        float s = 0.f, a = 0.f;
#pragma unroll
        for (int r = 0; r < 8; ++r) {
            float e = __expf(zb[r][i] - mx);
            s += e;
            a = fmaf(e, cc[r][i], a);
        }
        res[i] = a / s;
    }
    const long long w = (long long)blockIdx.x * 16 + win;
    float4 v = make_float4(res[0], res[1], res[2], res[3]);
    float* dst = out + w * HD_ + lane * 4;
    *(float4*)dst = v;
    if (write_second) *(float4*)(dst + out_half) = v;
}

extern "C" void kernel_launch(void* const* d_in, const int* in_sizes, int n_in,
                              void* d_out, int out_size)
{
    const float* h    = (const float*)d_in[0];
    const float* wkv  = (const float*)d_in[1];
    const float* wz   = (const float*)d_in[2];
    const float* bias = (const float*)d_in[3];

    const int rows = in_sizes[0] / D_;              // 32768
    const int base = (rows / 8) * HD_;              // 524288
    const int write_second = (out_size >= 2 * base) ? 1 : 0;

    convert_w<<<512, 256>>>((const float4*)wkv, (const float4*)wz);

    cudaFuncSetAttribute(heavy_compressor_v11,
                         cudaFuncAttributeMaxDynamicSharedMemorySize, SMEM_BYTES);
    heavy_compressor_v11<<<rows / CTA_M, 512, SMEM_BYTES>>>(
        h, bias, (float*)d_out, write_second, base);
}